// round 4
// baseline (speedup 1.0000x reference)
#include <cuda_runtime.h>
#include <cuda_bf16.h>
#include <math.h>

#define NE 2048
#define NX 3

// Scratch (allocation-free): all __device__ globals.
__device__ float g_s[NX][NE];        // static RHS (SC + last-column terms)
__device__ float g_Binv[NX*NX][NE];  // per-bin 3x3 inverse of B_i
__device__ float g_c[NE];            // c_j = dy*E_j
__device__ float g_F[2][NX][NE];     // double-buffered solution
__device__ float g_wF[2][NX][NE];    // double-buffered c_j*F_j (col NE-1 == 0)
__device__ __nv_bfloat16 g_Kh[9ull * NE * NE];  // bf16 copy of K (upper part written)

__device__ __forceinline__ float4 ld4(const float* __restrict__ p, int j) {
    return *reinterpret_cast<const float4*>(p + j);
}

// ---------------------------------------------------------------------------
// Setup: dy, src_last, F[:,NE-1], c_j, B_i^{-1}, s, initial guess F0 = Binv*s
// ---------------------------------------------------------------------------
__global__ __launch_bounds__(256) void setup_kernel(
    const float* __restrict__ E, const float* __restrict__ R,
    const float* __restrict__ K, const float* __restrict__ S0,
    const float* __restrict__ SC)
{
    int i = blockIdx.x * blockDim.x + threadIdx.x;
    if (i >= NE) return;

    const float dy = logf(E[NE-1] / E[0]) / (float)(NE - 1);

    float srcl[NX];
#pragma unroll
    for (int p = 0; p < NX; p++) srcl[p] = S0[p] / R[p*NE + NE-1];

    float Flast[NX];
#pragma unroll
    for (int x = 0; x < NX; x++) {
        float acc = SC[x*NE + NE-1];
#pragma unroll
        for (int p = 0; p < NX; p++)
            acc += K[((size_t)((x*NX + p)*NE + (NE-1)))*NE + (NE-1)] * srcl[p];
        Flast[x] = acc / R[x*NE + NE-1];
    }

    if (i == NE-1) {
        g_c[NE-1] = dy * E[NE-1];
#pragma unroll
        for (int x = 0; x < NX; x++) {
            g_F[0][x][NE-1] = Flast[x];
            g_F[1][x][NE-1] = Flast[x];
            g_wF[0][x][NE-1] = 0.0f;   // j=NE-1 handled inside s, never in matvec
            g_wF[1][x][NE-1] = 0.0f;
        }
        return;
    }

    const float ci = dy * E[i];
    g_c[i] = ci;
    const float w_last = 0.5f * dy * E[NE-1];

    float Bm[3][3];
    float sv[NX];
#pragma unroll
    for (int x = 0; x < NX; x++) {
        float acc = SC[x*NE + i];
#pragma unroll
        for (int p = 0; p < NX; p++) {
            size_t rb = ((size_t)((x*NX + p)*NE + i)) * NE;
            float Kii = K[rb + i];
            float Kil = K[rb + NE-1];
            Bm[x][p] = -0.5f * ci * Kii + ((x == p) ? R[x*NE + i] : 0.0f);
            acc += Kil * (w_last * Flast[p] + srcl[p]);
        }
        sv[x] = acc;
    }

    // 3x3 inverse (adjugate / det)
    float c00 = Bm[1][1]*Bm[2][2] - Bm[1][2]*Bm[2][1];
    float c01 = Bm[1][2]*Bm[2][0] - Bm[1][0]*Bm[2][2];
    float c02 = Bm[1][0]*Bm[2][1] - Bm[1][1]*Bm[2][0];
    float det = Bm[0][0]*c00 + Bm[0][1]*c01 + Bm[0][2]*c02;
    float id  = 1.0f / det;
    float inv[3][3];
    inv[0][0] = c00 * id;
    inv[0][1] = (Bm[0][2]*Bm[2][1] - Bm[0][1]*Bm[2][2]) * id;
    inv[0][2] = (Bm[0][1]*Bm[1][2] - Bm[0][2]*Bm[1][1]) * id;
    inv[1][0] = c01 * id;
    inv[1][1] = (Bm[0][0]*Bm[2][2] - Bm[0][2]*Bm[2][0]) * id;
    inv[1][2] = (Bm[0][2]*Bm[1][0] - Bm[0][0]*Bm[1][2]) * id;
    inv[2][0] = c02 * id;
    inv[2][1] = (Bm[0][1]*Bm[2][0] - Bm[0][0]*Bm[2][1]) * id;
    inv[2][2] = (Bm[0][0]*Bm[1][1] - Bm[0][1]*Bm[1][0]) * id;

#pragma unroll
    for (int x = 0; x < NX; x++) {
        g_s[x][i] = sv[x];
#pragma unroll
        for (int p = 0; p < NX; p++) g_Binv[x*NX + p][i] = inv[x][p];
    }

    // Initial guess: F0 = Binv * s
#pragma unroll
    for (int x = 0; x < NX; x++) {
        float f = inv[x][0]*sv[0] + inv[x][1]*sv[1] + inv[x][2]*sv[2];
        g_F[0][x][i]  = f;
        g_wF[0][x][i] = ci * f;
    }
}

// ---------------------------------------------------------------------------
// Shared epilogue: block-reduce y, apply Binv, write F/wF.
// ---------------------------------------------------------------------------
__device__ __forceinline__ void row_epilogue(
    int i, int dst, float y0, float y1, float y2,
    float red[3][8], int tid, int lane, int warp)
{
#pragma unroll
    for (int o = 16; o > 0; o >>= 1) {
        y0 += __shfl_xor_sync(0xffffffffu, y0, o);
        y1 += __shfl_xor_sync(0xffffffffu, y1, o);
        y2 += __shfl_xor_sync(0xffffffffu, y2, o);
    }
    if (lane == 0) { red[0][warp] = y0; red[1][warp] = y1; red[2][warp] = y2; }
    __syncthreads();

    if (tid == 0) {
        float s0 = g_s[0][i], s1 = g_s[1][i], s2 = g_s[2][i];
#pragma unroll
        for (int w = 0; w < 8; w++) {
            s0 += red[0][w]; s1 += red[1][w]; s2 += red[2][w];
        }
        float f0 = g_Binv[0][i]*s0 + g_Binv[1][i]*s1 + g_Binv[2][i]*s2;
        float f1 = g_Binv[3][i]*s0 + g_Binv[4][i]*s1 + g_Binv[5][i]*s2;
        float f2 = g_Binv[6][i]*s0 + g_Binv[7][i]*s1 + g_Binv[8][i]*s2;
        float ci = g_c[i];
        g_F[dst][0][i]  = f0;  g_wF[dst][0][i] = ci * f0;
        g_F[dst][1][i]  = f1;  g_wF[dst][1][i] = ci * f1;
        g_F[dst][2][i]  = f2;  g_wF[dst][2][i] = ci * f2;
    }
    __syncthreads();   // smem reuse guard
}

// ---------------------------------------------------------------------------
// Sweep 1 (fp32 K) + conversion: reads fp32 K (cold), stores bf16 copy of the
// 8-aligned upper part of each row while accumulating the matvec.
// ---------------------------------------------------------------------------
__device__ __forceinline__ void conv_row(
    int i, const float* __restrict__ K, int src, int dst,
    float red[3][8], int tid, int lane, int warp)
{
    const float* __restrict__ wf0 = g_wF[src][0];
    const float* __restrict__ wf1 = g_wF[src][1];
    const float* __restrict__ wf2 = g_wF[src][2];

    float y0 = 0.f, y1 = 0.f, y2 = 0.f;
    int jv = (i + 1) & ~7;           // 8-aligned start (bf16 chunks are 8-wide)
    int jb = jv + 4 * tid;

#define CONV1(M, Y, W)                                                         \
    do {                                                                       \
        const float* kp = K + ((size_t)((M)*NE + i))*NE;                       \
        float4 kk = ld4(kp, jb);                                               \
        Y += kk.x*W.x + kk.y*W.y + kk.z*W.z + kk.w*W.w;                        \
        __nv_bfloat162 h01 = __floats2bfloat162_rn(kk.x, kk.y);                \
        __nv_bfloat162 h23 = __floats2bfloat162_rn(kk.z, kk.w);                \
        uint2 pk = make_uint2(*(unsigned*)&h01, *(unsigned*)&h23);             \
        *reinterpret_cast<uint2*>(&g_Kh[((size_t)((M)*NE + i))*NE + jb]) = pk; \
    } while (0)

#define CONVALL(W0, W1, W2)                                                    \
    do {                                                                       \
        CONV1(0, y0, W0); CONV1(1, y0, W1); CONV1(2, y0, W2);                  \
        CONV1(3, y1, W0); CONV1(4, y1, W1); CONV1(5, y1, W2);                  \
        CONV1(6, y2, W0); CONV1(7, y2, W1); CONV1(8, y2, W2);                  \
    } while (0)

    if (jb < NE) {
        // first pass: mask w where j <= i (spans at most the first 8-block)
        float4 w0 = ld4(wf0, jb), w1 = ld4(wf1, jb), w2 = ld4(wf2, jb);
        if (jb + 0 <= i) { w0.x = 0.f; w1.x = 0.f; w2.x = 0.f; }
        if (jb + 1 <= i) { w0.y = 0.f; w1.y = 0.f; w2.y = 0.f; }
        if (jb + 2 <= i) { w0.z = 0.f; w1.z = 0.f; w2.z = 0.f; }
        if (jb + 3 <= i) { w0.w = 0.f; w1.w = 0.f; w2.w = 0.f; }
        CONVALL(w0, w1, w2);
        jb += 4 * 256;
    }
    for (; jb < NE; jb += 4 * 256) {
        float4 w0 = ld4(wf0, jb), w1 = ld4(wf1, jb), w2 = ld4(wf2, jb);
        CONVALL(w0, w1, w2);
    }
#undef CONVALL
#undef CONV1

    row_epilogue(i, dst, y0, y1, y2, red, tid, lane, warp);
}

__global__ __launch_bounds__(256) void iter_conv_kernel(
    const float* __restrict__ K, int src, int dst)
{
    __shared__ float red[3][8];
    int tid = threadIdx.x, lane = tid & 31, warp = tid >> 5;
    int b = blockIdx.x;
    conv_row(b,          K, src, dst, red, tid, lane, warp);
    conv_row(NE - 2 - b, K, src, dst, red, tid, lane, warp);
}

// ---------------------------------------------------------------------------
// bf16 sweep: each thread owns exactly one 8-wide chunk of the row
// (256 threads x 8 = 2048 = NE). Half the bytes of the fp32 sweep.
// ---------------------------------------------------------------------------
__device__ __forceinline__ void bf16_row(
    int i, int src, int dst,
    float red[3][8], int tid, int lane, int warp)
{
    const float* __restrict__ wf0 = g_wF[src][0];
    const float* __restrict__ wf1 = g_wF[src][1];
    const float* __restrict__ wf2 = g_wF[src][2];

    float y0 = 0.f, y1 = 0.f, y2 = 0.f;
    int jv = (i + 1) & ~7;
    int jb = jv + 8 * tid;

    if (jb < NE) {
        float w0[8], w1[8], w2[8];
        {
            float4 a = ld4(wf0, jb), b4 = ld4(wf0, jb + 4);
            w0[0]=a.x; w0[1]=a.y; w0[2]=a.z; w0[3]=a.w;
            w0[4]=b4.x; w0[5]=b4.y; w0[6]=b4.z; w0[7]=b4.w;
            a = ld4(wf1, jb); b4 = ld4(wf1, jb + 4);
            w1[0]=a.x; w1[1]=a.y; w1[2]=a.z; w1[3]=a.w;
            w1[4]=b4.x; w1[5]=b4.y; w1[6]=b4.z; w1[7]=b4.w;
            a = ld4(wf2, jb); b4 = ld4(wf2, jb + 4);
            w2[0]=a.x; w2[1]=a.y; w2[2]=a.z; w2[3]=a.w;
            w2[4]=b4.x; w2[5]=b4.y; w2[6]=b4.z; w2[7]=b4.w;
        }
        if (jb <= i) {   // only the first chunk can contain j <= i
#pragma unroll
            for (int e = 0; e < 8; e++)
                if (jb + e <= i) { w0[e]=0.f; w1[e]=0.f; w2[e]=0.f; }
        }

#define BACC(M, Y, W)                                                          \
        do {                                                                   \
            uint4 q = *reinterpret_cast<const uint4*>(                         \
                &g_Kh[((size_t)((M)*NE + i))*NE + jb]);                        \
            float2 f;                                                          \
            f = __bfloat1622float2(*(__nv_bfloat162*)&q.x);                    \
            Y += f.x*W[0] + f.y*W[1];                                          \
            f = __bfloat1622float2(*(__nv_bfloat162*)&q.y);                    \
            Y += f.x*W[2] + f.y*W[3];                                          \
            f = __bfloat1622float2(*(__nv_bfloat162*)&q.z);                    \
            Y += f.x*W[4] + f.y*W[5];                                          \
            f = __bfloat1622float2(*(__nv_bfloat162*)&q.w);                    \
            Y += f.x*W[6] + f.y*W[7];                                          \
        } while (0)

        BACC(0, y0, w0); BACC(1, y0, w1); BACC(2, y0, w2);
        BACC(3, y1, w0); BACC(4, y1, w1); BACC(5, y1, w2);
        BACC(6, y2, w0); BACC(7, y2, w1); BACC(8, y2, w2);
#undef BACC
    }

    row_epilogue(i, dst, y0, y1, y2, red, tid, lane, warp);
}

__global__ __launch_bounds__(256) void iter_bf16_kernel(int src, int dst)
{
    __shared__ float red[3][8];
    int tid = threadIdx.x, lane = tid & 31, warp = tid >> 5;
    int b = blockIdx.x;
    bf16_row(b,          src, dst, red, tid, lane, warp);
    bf16_row(NE - 2 - b, src, dst, red, tid, lane, warp);
}

// ---------------------------------------------------------------------------
// Finalize: out[0,:] = E_grid; out[1+x,:] = max(F,0)
// ---------------------------------------------------------------------------
__global__ __launch_bounds__(256) void final_kernel(
    const float* __restrict__ E, float* __restrict__ out, int src)
{
    int i = blockIdx.x * blockDim.x + threadIdx.x;
    if (i >= NE) return;
    out[i] = E[i];
#pragma unroll
    for (int x = 0; x < NX; x++) {
        float f = g_F[src][x][i];
        out[(x + 1) * NE + i] = (f > 0.0f) ? f : 0.0f;
    }
}

extern "C" void kernel_launch(void* const* d_in, const int* in_sizes, int n_in,
                              void* d_out, int out_size)
{
    const float* E  = (const float*)d_in[0];
    const float* R  = (const float*)d_in[1];
    const float* K  = (const float*)d_in[2];
    const float* S0 = (const float*)d_in[3];
    const float* SC = (const float*)d_in[4];
    float* out = (float*)d_out;

    setup_kernel<<<(NE + 255) / 256, 256>>>(E, R, K, S0, SC);

    // Sweep 1: fp32 matvec + bf16 conversion (compulsory cold read of K)
    iter_conv_kernel<<<NE/2, 256>>>(K, 0, 1);

    // Sweeps 2-5: bf16 matvec (L2-resident, half bytes)
    int src = 1;
    for (int it = 0; it < 4; it++) {
        iter_bf16_kernel<<<NE/2, 256>>>(src, 1 - src);
        src = 1 - src;
    }

    final_kernel<<<(NE + 255) / 256, 256>>>(E, out, src);
}

// round 5
// speedup vs baseline: 1.4816x; 1.4816x over previous
#include <cuda_runtime.h>
#include <math.h>

#define NE 2048
#define NX 3

// Scratch (allocation-free): all __device__ globals.
__device__ float g_s[NX][NE];        // static RHS (SC + last-column terms)
__device__ float g_s2[NX][NE];       // extended RHS for lower rows (s + upper-half coupling)
__device__ float g_Binv[NX*NX][NE];  // per-bin 3x3 inverse of B_i
__device__ float g_c[NE];            // c_j = dy*E_j
__device__ float g_F[2][NX][NE];     // double-buffered solution
__device__ float g_wF[2][NX][NE];    // double-buffered c_j*F_j (col NE-1 == 0 sentinel)

__device__ __forceinline__ float4 ld4(const float* __restrict__ p, int j) {
    return *reinterpret_cast<const float4*>(p + j);
}

// ---------------------------------------------------------------------------
// Setup: dy, src_last, F[:,NE-1], c_j, B_i^{-1}, s, initial guess F0 = Binv*s
// ---------------------------------------------------------------------------
__global__ __launch_bounds__(256) void setup_kernel(
    const float* __restrict__ E, const float* __restrict__ R,
    const float* __restrict__ K, const float* __restrict__ S0,
    const float* __restrict__ SC)
{
    int i = blockIdx.x * blockDim.x + threadIdx.x;
    if (i >= NE) return;

    const float dy = logf(E[NE-1] / E[0]) / (float)(NE - 1);

    float srcl[NX];
#pragma unroll
    for (int p = 0; p < NX; p++) srcl[p] = S0[p] / R[p*NE + NE-1];

    float Flast[NX];
#pragma unroll
    for (int x = 0; x < NX; x++) {
        float acc = SC[x*NE + NE-1];
#pragma unroll
        for (int p = 0; p < NX; p++)
            acc += K[((size_t)((x*NX + p)*NE + (NE-1)))*NE + (NE-1)] * srcl[p];
        Flast[x] = acc / R[x*NE + NE-1];
    }

    if (i == NE-1) {
        g_c[NE-1] = dy * E[NE-1];
#pragma unroll
        for (int x = 0; x < NX; x++) {
            g_F[0][x][NE-1] = Flast[x];
            g_F[1][x][NE-1] = Flast[x];
            g_wF[0][x][NE-1] = 0.0f;   // j=NE-1 handled inside s, never in matvec
            g_wF[1][x][NE-1] = 0.0f;
        }
        return;
    }

    const float ci = dy * E[i];
    g_c[i] = ci;
    const float w_last = 0.5f * dy * E[NE-1];

    float Bm[3][3];
    float sv[NX];
#pragma unroll
    for (int x = 0; x < NX; x++) {
        float acc = SC[x*NE + i];
#pragma unroll
        for (int p = 0; p < NX; p++) {
            size_t rb = ((size_t)((x*NX + p)*NE + i)) * NE;
            float Kii = K[rb + i];
            float Kil = K[rb + NE-1];
            Bm[x][p] = -0.5f * ci * Kii + ((x == p) ? R[x*NE + i] : 0.0f);
            acc += Kil * (w_last * Flast[p] + srcl[p]);
        }
        sv[x] = acc;
    }

    // 3x3 inverse (adjugate / det)
    float c00 = Bm[1][1]*Bm[2][2] - Bm[1][2]*Bm[2][1];
    float c01 = Bm[1][2]*Bm[2][0] - Bm[1][0]*Bm[2][2];
    float c02 = Bm[1][0]*Bm[2][1] - Bm[1][1]*Bm[2][0];
    float det = Bm[0][0]*c00 + Bm[0][1]*c01 + Bm[0][2]*c02;
    float id  = 1.0f / det;
    float inv[3][3];
    inv[0][0] = c00 * id;
    inv[0][1] = (Bm[0][2]*Bm[2][1] - Bm[0][1]*Bm[2][2]) * id;
    inv[0][2] = (Bm[0][1]*Bm[1][2] - Bm[0][2]*Bm[1][1]) * id;
    inv[1][0] = c01 * id;
    inv[1][1] = (Bm[0][0]*Bm[2][2] - Bm[0][2]*Bm[2][0]) * id;
    inv[1][2] = (Bm[0][2]*Bm[1][0] - Bm[0][0]*Bm[1][2]) * id;
    inv[2][0] = c02 * id;
    inv[2][1] = (Bm[0][1]*Bm[2][0] - Bm[0][0]*Bm[2][1]) * id;
    inv[2][2] = (Bm[0][0]*Bm[1][1] - Bm[0][1]*Bm[1][0]) * id;

#pragma unroll
    for (int x = 0; x < NX; x++) {
        g_s[x][i] = sv[x];
#pragma unroll
        for (int p = 0; p < NX; p++) g_Binv[x*NX + p][i] = inv[x][p];
    }

    // Initial guess: F0 = Binv * s
#pragma unroll
    for (int x = 0; x < NX; x++) {
        float f = inv[x][0]*sv[0] + inv[x][1]*sv[1] + inv[x][2]*sv[2];
        g_F[0][x][i]  = f;
        g_wF[0][x][i] = ci * f;
    }
}

// ---------------------------------------------------------------------------
// 9-stream fma accumulate over one 4-wide chunk
// ---------------------------------------------------------------------------
#define ACCUM(JB, W0, W1, W2)                                                  \
    do {                                                                       \
        float4 kk;                                                             \
        kk = ld4(k00, JB); y0 += kk.x*W0.x + kk.y*W0.y + kk.z*W0.z + kk.w*W0.w;\
        kk = ld4(k01, JB); y0 += kk.x*W1.x + kk.y*W1.y + kk.z*W1.z + kk.w*W1.w;\
        kk = ld4(k02, JB); y0 += kk.x*W2.x + kk.y*W2.y + kk.z*W2.z + kk.w*W2.w;\
        kk = ld4(k10, JB); y1 += kk.x*W0.x + kk.y*W0.y + kk.z*W0.z + kk.w*W0.w;\
        kk = ld4(k11, JB); y1 += kk.x*W1.x + kk.y*W1.y + kk.z*W1.z + kk.w*W1.w;\
        kk = ld4(k12, JB); y1 += kk.x*W2.x + kk.y*W2.y + kk.z*W2.z + kk.w*W2.w;\
        kk = ld4(k20, JB); y2 += kk.x*W0.x + kk.y*W0.y + kk.z*W0.z + kk.w*W0.w;\
        kk = ld4(k21, JB); y2 += kk.x*W1.x + kk.y*W1.y + kk.z*W1.z + kk.w*W1.w;\
        kk = ld4(k22, JB); y2 += kk.x*W2.x + kk.y*W2.y + kk.z*W2.z + kk.w*W2.w;\
    } while (0)

#define DECLARE_K_STREAMS(K, i)                                                \
    const float* __restrict__ k00 = K + ((size_t)((0*NX+0)*NE + i))*NE;        \
    const float* __restrict__ k01 = K + ((size_t)((0*NX+1)*NE + i))*NE;        \
    const float* __restrict__ k02 = K + ((size_t)((0*NX+2)*NE + i))*NE;        \
    const float* __restrict__ k10 = K + ((size_t)((1*NX+0)*NE + i))*NE;        \
    const float* __restrict__ k11 = K + ((size_t)((1*NX+1)*NE + i))*NE;        \
    const float* __restrict__ k12 = K + ((size_t)((1*NX+2)*NE + i))*NE;        \
    const float* __restrict__ k20 = K + ((size_t)((2*NX+0)*NE + i))*NE;        \
    const float* __restrict__ k21 = K + ((size_t)((2*NX+1)*NE + i))*NE;        \
    const float* __restrict__ k22 = K + ((size_t)((2*NX+2)*NE + i))*NE;

// ---------------------------------------------------------------------------
// Ranged sweep row: y = sum_{p, j in (i, col_hi)} K[x][p][i][j] * wF[p][j],
// F_new[:,i] = Binv_i * (s_in[:,i] + y)
// ---------------------------------------------------------------------------
__device__ __forceinline__ void sweep_row(
    int i, const float* __restrict__ K, int src, int dst, int col_hi,
    int use_s2, float red[3][8], int tid, int lane, int warp)
{
    const float* __restrict__ wf0 = g_wF[src][0];
    const float* __restrict__ wf1 = g_wF[src][1];
    const float* __restrict__ wf2 = g_wF[src][2];
    DECLARE_K_STREAMS(K, i)

    float y0 = 0.f, y1 = 0.f, y2 = 0.f;
    int jv = (i + 1) & ~3;           // 16B-aligned start
    int jb = jv + 4 * tid;

    if (jb < col_hi) {
        // first pass: mask elements with j <= i
        float4 w0 = ld4(wf0, jb), w1 = ld4(wf1, jb), w2 = ld4(wf2, jb);
        if (jb + 0 <= i) { w0.x = 0.f; w1.x = 0.f; w2.x = 0.f; }
        if (jb + 1 <= i) { w0.y = 0.f; w1.y = 0.f; w2.y = 0.f; }
        if (jb + 2 <= i) { w0.z = 0.f; w1.z = 0.f; w2.z = 0.f; }
        if (jb + 3 <= i) { w0.w = 0.f; w1.w = 0.f; w2.w = 0.f; }
        ACCUM(jb, w0, w1, w2);
        jb += 4 * 256;
    }
    for (; jb < col_hi; jb += 4 * 256) {
        float4 w0 = ld4(wf0, jb), w1 = ld4(wf1, jb), w2 = ld4(wf2, jb);
        ACCUM(jb, w0, w1, w2);
    }

    // block reduce + apply Binv
#pragma unroll
    for (int o = 16; o > 0; o >>= 1) {
        y0 += __shfl_xor_sync(0xffffffffu, y0, o);
        y1 += __shfl_xor_sync(0xffffffffu, y1, o);
        y2 += __shfl_xor_sync(0xffffffffu, y2, o);
    }
    if (lane == 0) { red[0][warp] = y0; red[1][warp] = y1; red[2][warp] = y2; }
    __syncthreads();

    if (tid == 0) {
        float s0, s1, s2;
        if (use_s2) { s0 = g_s2[0][i]; s1 = g_s2[1][i]; s2 = g_s2[2][i]; }
        else        { s0 = g_s [0][i]; s1 = g_s [1][i]; s2 = g_s [2][i]; }
#pragma unroll
        for (int w = 0; w < 8; w++) {
            s0 += red[0][w]; s1 += red[1][w]; s2 += red[2][w];
        }
        float f0 = g_Binv[0][i]*s0 + g_Binv[1][i]*s1 + g_Binv[2][i]*s2;
        float f1 = g_Binv[3][i]*s0 + g_Binv[4][i]*s1 + g_Binv[5][i]*s2;
        float f2 = g_Binv[6][i]*s0 + g_Binv[7][i]*s1 + g_Binv[8][i]*s2;
        float ci = g_c[i];
        g_F[dst][0][i]  = f0;  g_wF[dst][0][i] = ci * f0;
        g_F[dst][1][i]  = f1;  g_wF[dst][1][i] = ci * f1;
        g_F[dst][2][i]  = f2;  g_wF[dst][2][i] = ci * f2;
    }
    __syncthreads();   // smem reuse guard
}

// Block b handles rows (row_lo + b) and (row_hi - b): constant work per block.
__global__ __launch_bounds__(256) void sweep_kernel(
    const float* __restrict__ K, int src, int dst,
    int row_lo, int row_hi, int col_hi, int use_s2)
{
    __shared__ float red[3][8];
    int tid = threadIdx.x, lane = tid & 31, warp = tid >> 5;
    int b = blockIdx.x;
    int r0 = row_lo + b;
    int r1 = row_hi - b;
    sweep_row(r0, K, src, dst, col_hi, use_s2, red, tid, lane, warp);
    if (r1 != r0)
        sweep_row(r1, K, src, dst, col_hi, use_s2, red, tid, lane, warp);
}

// ---------------------------------------------------------------------------
// Accumulate solved upper half into lower rows' RHS:
// g_s2[:,i] = g_s[:,i] + sum_{p, j in [1024,2048)} K[x][p][i][j]*wF[p][j]
// (wF[2047]==0 sentinel; j always > i since i < 1024)
// One block per row; 256 threads x 4 = exactly 1024 columns, single pass.
// ---------------------------------------------------------------------------
__global__ __launch_bounds__(256) void accum_kernel(
    const float* __restrict__ K, int src)
{
    __shared__ float red[3][8];
    int tid = threadIdx.x, lane = tid & 31, warp = tid >> 5;
    int i = blockIdx.x;              // 0..1023

    const float* __restrict__ wf0 = g_wF[src][0];
    const float* __restrict__ wf1 = g_wF[src][1];
    const float* __restrict__ wf2 = g_wF[src][2];
    DECLARE_K_STREAMS(K, i)

    float y0 = 0.f, y1 = 0.f, y2 = 0.f;
    int jb = NE/2 + 4 * tid;
    {
        float4 w0 = ld4(wf0, jb), w1 = ld4(wf1, jb), w2 = ld4(wf2, jb);
        ACCUM(jb, w0, w1, w2);
    }

#pragma unroll
    for (int o = 16; o > 0; o >>= 1) {
        y0 += __shfl_xor_sync(0xffffffffu, y0, o);
        y1 += __shfl_xor_sync(0xffffffffu, y1, o);
        y2 += __shfl_xor_sync(0xffffffffu, y2, o);
    }
    if (lane == 0) { red[0][warp] = y0; red[1][warp] = y1; red[2][warp] = y2; }
    __syncthreads();

    if (tid == 0) {
        float s0 = g_s[0][i], s1 = g_s[1][i], s2 = g_s[2][i];
#pragma unroll
        for (int w = 0; w < 8; w++) {
            s0 += red[0][w]; s1 += red[1][w]; s2 += red[2][w];
        }
        g_s2[0][i] = s0; g_s2[1][i] = s1; g_s2[2][i] = s2;
    }
}

// ---------------------------------------------------------------------------
// Finalize: out[0,:] = E_grid; out[1+x,:] = max(F,0)
// Lower rows (<1024) live in buffer 1, upper rows (>=1024) in buffer 0.
// ---------------------------------------------------------------------------
__global__ __launch_bounds__(256) void final_kernel(
    const float* __restrict__ E, float* __restrict__ out)
{
    int i = blockIdx.x * blockDim.x + threadIdx.x;
    if (i >= NE) return;
    out[i] = E[i];
    int buf = (i < NE/2) ? 1 : 0;
#pragma unroll
    for (int x = 0; x < NX; x++) {
        float f = g_F[buf][x][i];
        out[(x + 1) * NE + i] = (f > 0.0f) ? f : 0.0f;
    }
}

extern "C" void kernel_launch(void* const* d_in, const int* in_sizes, int n_in,
                              void* d_out, int out_size)
{
    const float* E  = (const float*)d_in[0];
    const float* R  = (const float*)d_in[1];
    const float* K  = (const float*)d_in[2];
    const float* S0 = (const float*)d_in[3];
    const float* SC = (const float*)d_in[4];
    float* out = (float*)d_out;

    setup_kernel<<<(NE + 255) / 256, 256>>>(E, R, K, S0, SC);

    // Phase 1: Jacobi on upper half (rows 1024..2046), j in (i, 2048).
    // 4 sweeps: 0->1, 1->0, 0->1, 1->0  (final in buffer 0)
    sweep_kernel<<<512, 256>>>(K, 0, 1, NE/2, NE-2, NE, 0);
    sweep_kernel<<<512, 256>>>(K, 1, 0, NE/2, NE-2, NE, 0);
    sweep_kernel<<<512, 256>>>(K, 0, 1, NE/2, NE-2, NE, 0);
    sweep_kernel<<<512, 256>>>(K, 1, 0, NE/2, NE-2, NE, 0);

    // Accumulate upper-half contributions into lower rows' RHS (reads buffer 0)
    accum_kernel<<<NE/2, 256>>>(K, 0);

    // Phase 2: Jacobi on lower half (rows 0..1023), j in (i, 1024), RHS = s2.
    // 3 sweeps: 0->1, 1->0, 0->1  (final in buffer 1)
    sweep_kernel<<<512, 256>>>(K, 0, 1, 0, NE/2 - 1, NE/2, 1);
    sweep_kernel<<<512, 256>>>(K, 1, 0, 0, NE/2 - 1, NE/2, 1);
    sweep_kernel<<<512, 256>>>(K, 0, 1, 0, NE/2 - 1, NE/2, 1);

    final_kernel<<<(NE + 255) / 256, 256>>>(E, out);
}

// round 6
// speedup vs baseline: 1.4825x; 1.0006x over previous
#include <cuda_runtime.h>
#include <math.h>

#define NE 2048
#define NX 3

// Scratch (allocation-free): all __device__ globals.
__device__ float g_s[NX][NE];        // static RHS (SC + last-column terms)
__device__ float g_s2[NX][NE];       // extended RHS for lower rows
__device__ float g_Binv[NX*NX][NE];  // per-bin 3x3 inverse of B_i
__device__ float g_c[NE];            // c_j = dy*E_j
__device__ float g_F[2][NX][NE];     // double-buffered solution
__device__ float g_wF[2][NX][NE];    // double-buffered c_j*F_j (col NE-1 == 0)
__device__ float g_sink;             // DCE guard for prefetch

__device__ __forceinline__ float4 ld4(const float* __restrict__ p, int j) {
    return *reinterpret_cast<const float4*>(p + j);
}

#define DECLARE_K_STREAMS(K, i)                                                \
    const float* __restrict__ k00 = K + ((size_t)((0*NX+0)*NE + i))*NE;        \
    const float* __restrict__ k01 = K + ((size_t)((0*NX+1)*NE + i))*NE;        \
    const float* __restrict__ k02 = K + ((size_t)((0*NX+2)*NE + i))*NE;        \
    const float* __restrict__ k10 = K + ((size_t)((1*NX+0)*NE + i))*NE;        \
    const float* __restrict__ k11 = K + ((size_t)((1*NX+1)*NE + i))*NE;        \
    const float* __restrict__ k12 = K + ((size_t)((1*NX+2)*NE + i))*NE;        \
    const float* __restrict__ k20 = K + ((size_t)((2*NX+0)*NE + i))*NE;        \
    const float* __restrict__ k21 = K + ((size_t)((2*NX+1)*NE + i))*NE;        \
    const float* __restrict__ k22 = K + ((size_t)((2*NX+2)*NE + i))*NE;

#define ACCUM(JB, W0, W1, W2)                                                  \
    do {                                                                       \
        float4 kk;                                                             \
        kk = ld4(k00, JB); y0 += kk.x*W0.x + kk.y*W0.y + kk.z*W0.z + kk.w*W0.w;\
        kk = ld4(k01, JB); y0 += kk.x*W1.x + kk.y*W1.y + kk.z*W1.z + kk.w*W1.w;\
        kk = ld4(k02, JB); y0 += kk.x*W2.x + kk.y*W2.y + kk.z*W2.z + kk.w*W2.w;\
        kk = ld4(k10, JB); y1 += kk.x*W0.x + kk.y*W0.y + kk.z*W0.z + kk.w*W0.w;\
        kk = ld4(k11, JB); y1 += kk.x*W1.x + kk.y*W1.y + kk.z*W1.z + kk.w*W1.w;\
        kk = ld4(k12, JB); y1 += kk.x*W2.x + kk.y*W2.y + kk.z*W2.z + kk.w*W2.w;\
        kk = ld4(k20, JB); y2 += kk.x*W0.x + kk.y*W0.y + kk.z*W0.z + kk.w*W0.w;\
        kk = ld4(k21, JB); y2 += kk.x*W1.x + kk.y*W1.y + kk.z*W1.z + kk.w*W1.w;\
        kk = ld4(k22, JB); y2 += kk.x*W2.x + kk.y*W2.y + kk.z*W2.z + kk.w*W2.w;\
    } while (0)

// ---------------------------------------------------------------------------
// Setup math for one bin i (unchanged from R4)
// ---------------------------------------------------------------------------
__device__ __forceinline__ void setup_bin(
    int i, const float* __restrict__ E, const float* __restrict__ R,
    const float* __restrict__ K, const float* __restrict__ S0,
    const float* __restrict__ SC)
{
    const float dy = logf(E[NE-1] / E[0]) / (float)(NE - 1);

    float srcl[NX];
#pragma unroll
    for (int p = 0; p < NX; p++) srcl[p] = S0[p] / R[p*NE + NE-1];

    float Flast[NX];
#pragma unroll
    for (int x = 0; x < NX; x++) {
        float acc = SC[x*NE + NE-1];
#pragma unroll
        for (int p = 0; p < NX; p++)
            acc += K[((size_t)((x*NX + p)*NE + (NE-1)))*NE + (NE-1)] * srcl[p];
        Flast[x] = acc / R[x*NE + NE-1];
    }

    if (i == NE-1) {
        g_c[NE-1] = dy * E[NE-1];
#pragma unroll
        for (int x = 0; x < NX; x++) {
            g_F[0][x][NE-1] = Flast[x];
            g_F[1][x][NE-1] = Flast[x];
            g_wF[0][x][NE-1] = 0.0f;
            g_wF[1][x][NE-1] = 0.0f;
        }
        return;
    }

    const float ci = dy * E[i];
    g_c[i] = ci;
    const float w_last = 0.5f * dy * E[NE-1];

    float Bm[3][3];
    float sv[NX];
#pragma unroll
    for (int x = 0; x < NX; x++) {
        float acc = SC[x*NE + i];
#pragma unroll
        for (int p = 0; p < NX; p++) {
            size_t rb = ((size_t)((x*NX + p)*NE + i)) * NE;
            float Kii = K[rb + i];
            float Kil = K[rb + NE-1];
            Bm[x][p] = -0.5f * ci * Kii + ((x == p) ? R[x*NE + i] : 0.0f);
            acc += Kil * (w_last * Flast[p] + srcl[p]);
        }
        sv[x] = acc;
    }

    float c00 = Bm[1][1]*Bm[2][2] - Bm[1][2]*Bm[2][1];
    float c01 = Bm[1][2]*Bm[2][0] - Bm[1][0]*Bm[2][2];
    float c02 = Bm[1][0]*Bm[2][1] - Bm[1][1]*Bm[2][0];
    float det = Bm[0][0]*c00 + Bm[0][1]*c01 + Bm[0][2]*c02;
    float id  = 1.0f / det;
    float inv[3][3];
    inv[0][0] = c00 * id;
    inv[0][1] = (Bm[0][2]*Bm[2][1] - Bm[0][1]*Bm[2][2]) * id;
    inv[0][2] = (Bm[0][1]*Bm[1][2] - Bm[0][2]*Bm[1][1]) * id;
    inv[1][0] = c01 * id;
    inv[1][1] = (Bm[0][0]*Bm[2][2] - Bm[0][2]*Bm[2][0]) * id;
    inv[1][2] = (Bm[0][2]*Bm[1][0] - Bm[0][0]*Bm[1][2]) * id;
    inv[2][0] = c02 * id;
    inv[2][1] = (Bm[0][1]*Bm[2][0] - Bm[0][0]*Bm[2][1]) * id;
    inv[2][2] = (Bm[0][0]*Bm[1][1] - Bm[0][1]*Bm[1][0]) * id;

#pragma unroll
    for (int x = 0; x < NX; x++) {
        g_s[x][i] = sv[x];
#pragma unroll
        for (int p = 0; p < NX; p++) g_Binv[x*NX + p][i] = inv[x][p];
    }

#pragma unroll
    for (int x = 0; x < NX; x++) {
        float f = inv[x][0]*sv[0] + inv[x][1]*sv[1] + inv[x][2]*sv[2];
        g_F[0][x][i]  = f;
        g_wF[0][x][i] = ci * f;
    }
}

// ---------------------------------------------------------------------------
// Prefetch one K row's upper part (cols i&~3 .. 2048, all 9 streams) into L2.
// ---------------------------------------------------------------------------
__device__ __forceinline__ float prefetch_row(
    int i, const float* __restrict__ K, int tid)
{
    DECLARE_K_STREAMS(K, i)
    float s = 0.f;
    for (int jb = (i & ~3) + 4 * tid; jb < NE; jb += 4 * 256) {
        float4 a;
        a = ld4(k00, jb); s += a.x + a.y + a.z + a.w;
        a = ld4(k01, jb); s += a.x + a.y + a.z + a.w;
        a = ld4(k02, jb); s += a.x + a.y + a.z + a.w;
        a = ld4(k10, jb); s += a.x + a.y + a.z + a.w;
        a = ld4(k11, jb); s += a.x + a.y + a.z + a.w;
        a = ld4(k12, jb); s += a.x + a.y + a.z + a.w;
        a = ld4(k20, jb); s += a.x + a.y + a.z + a.w;
        a = ld4(k21, jb); s += a.x + a.y + a.z + a.w;
        a = ld4(k22, jb); s += a.x + a.y + a.z + a.w;
    }
    return s;
}

// Combined setup (blocks 0..7) + full upper-triangle L2 prefetch (blocks 8..).
__global__ __launch_bounds__(256) void setup_prefetch_kernel(
    const float* __restrict__ E, const float* __restrict__ R,
    const float* __restrict__ K, const float* __restrict__ S0,
    const float* __restrict__ SC)
{
    int tid = threadIdx.x;
    if (blockIdx.x < 8) {
        int i = blockIdx.x * 256 + tid;
        setup_bin(i, E, R, K, S0, SC);
        return;
    }
    int pb = blockIdx.x - 8;         // 0..1023
    int r0 = pb;
    int r1 = 2046 - pb;
    float s = prefetch_row(r0, K, tid);
    if (r1 != r0) s += prefetch_row(r1, K, tid);
    if (s == -12345.678f) g_sink = s;   // never true; keeps loads alive
}

// ---------------------------------------------------------------------------
// Ranged sweep row: y = sum_{p, j in (i, col_hi)} K[x][p][i][j] * wF[p][j],
// F_new[:,i] = Binv_i * (s_in[:,i] + y)
// ---------------------------------------------------------------------------
__device__ __forceinline__ void sweep_row(
    int i, const float* __restrict__ K, int src, int dst, int col_hi,
    int use_s2, float red[3][8], int tid, int lane, int warp)
{
    const float* __restrict__ wf0 = g_wF[src][0];
    const float* __restrict__ wf1 = g_wF[src][1];
    const float* __restrict__ wf2 = g_wF[src][2];
    DECLARE_K_STREAMS(K, i)

    float y0 = 0.f, y1 = 0.f, y2 = 0.f;
    int jv = (i + 1) & ~3;
    int jb = jv + 4 * tid;

    if (jb < col_hi) {
        float4 w0 = ld4(wf0, jb), w1 = ld4(wf1, jb), w2 = ld4(wf2, jb);
        if (jb + 0 <= i) { w0.x = 0.f; w1.x = 0.f; w2.x = 0.f; }
        if (jb + 1 <= i) { w0.y = 0.f; w1.y = 0.f; w2.y = 0.f; }
        if (jb + 2 <= i) { w0.z = 0.f; w1.z = 0.f; w2.z = 0.f; }
        if (jb + 3 <= i) { w0.w = 0.f; w1.w = 0.f; w2.w = 0.f; }
        ACCUM(jb, w0, w1, w2);
        jb += 4 * 256;
    }
    for (; jb < col_hi; jb += 4 * 256) {
        float4 w0 = ld4(wf0, jb), w1 = ld4(wf1, jb), w2 = ld4(wf2, jb);
        ACCUM(jb, w0, w1, w2);
    }

#pragma unroll
    for (int o = 16; o > 0; o >>= 1) {
        y0 += __shfl_xor_sync(0xffffffffu, y0, o);
        y1 += __shfl_xor_sync(0xffffffffu, y1, o);
        y2 += __shfl_xor_sync(0xffffffffu, y2, o);
    }
    if (lane == 0) { red[0][warp] = y0; red[1][warp] = y1; red[2][warp] = y2; }
    __syncthreads();

    if (tid == 0) {
        float s0, s1, s2;
        if (use_s2) { s0 = g_s2[0][i]; s1 = g_s2[1][i]; s2 = g_s2[2][i]; }
        else        { s0 = g_s [0][i]; s1 = g_s [1][i]; s2 = g_s [2][i]; }
#pragma unroll
        for (int w = 0; w < 8; w++) {
            s0 += red[0][w]; s1 += red[1][w]; s2 += red[2][w];
        }
        float f0 = g_Binv[0][i]*s0 + g_Binv[1][i]*s1 + g_Binv[2][i]*s2;
        float f1 = g_Binv[3][i]*s0 + g_Binv[4][i]*s1 + g_Binv[5][i]*s2;
        float f2 = g_Binv[6][i]*s0 + g_Binv[7][i]*s1 + g_Binv[8][i]*s2;
        float ci = g_c[i];
        g_F[dst][0][i]  = f0;  g_wF[dst][0][i] = ci * f0;
        g_F[dst][1][i]  = f1;  g_wF[dst][1][i] = ci * f1;
        g_F[dst][2][i]  = f2;  g_wF[dst][2][i] = ci * f2;
    }
    __syncthreads();
}

__global__ __launch_bounds__(256) void sweep_kernel(
    const float* __restrict__ K, int src, int dst,
    int row_lo, int row_hi, int col_hi, int use_s2)
{
    __shared__ float red[3][8];
    int tid = threadIdx.x, lane = tid & 31, warp = tid >> 5;
    int b = blockIdx.x;
    int r0 = row_lo + b;
    int r1 = row_hi - b;
    sweep_row(r0, K, src, dst, col_hi, use_s2, red, tid, lane, warp);
    if (r1 != r0)
        sweep_row(r1, K, src, dst, col_hi, use_s2, red, tid, lane, warp);
}

// ---------------------------------------------------------------------------
// Accumulate solved upper half into lower rows' RHS:
// g_s2[:,i] = g_s[:,i] + sum_{p, j in [1024,2048)} K[x][p][i][j]*wF[p][j]
// ---------------------------------------------------------------------------
__global__ __launch_bounds__(256) void accum_kernel(
    const float* __restrict__ K, int src)
{
    __shared__ float red[3][8];
    int tid = threadIdx.x, lane = tid & 31, warp = tid >> 5;
    int i = blockIdx.x;              // 0..1023

    const float* __restrict__ wf0 = g_wF[src][0];
    const float* __restrict__ wf1 = g_wF[src][1];
    const float* __restrict__ wf2 = g_wF[src][2];
    DECLARE_K_STREAMS(K, i)

    float y0 = 0.f, y1 = 0.f, y2 = 0.f;
    int jb = NE/2 + 4 * tid;
    {
        float4 w0 = ld4(wf0, jb), w1 = ld4(wf1, jb), w2 = ld4(wf2, jb);
        ACCUM(jb, w0, w1, w2);
    }

#pragma unroll
    for (int o = 16; o > 0; o >>= 1) {
        y0 += __shfl_xor_sync(0xffffffffu, y0, o);
        y1 += __shfl_xor_sync(0xffffffffu, y1, o);
        y2 += __shfl_xor_sync(0xffffffffu, y2, o);
    }
    if (lane == 0) { red[0][warp] = y0; red[1][warp] = y1; red[2][warp] = y2; }
    __syncthreads();

    if (tid == 0) {
        float s0 = g_s[0][i], s1 = g_s[1][i], s2 = g_s[2][i];
#pragma unroll
        for (int w = 0; w < 8; w++) {
            s0 += red[0][w]; s1 += red[1][w]; s2 += red[2][w];
        }
        g_s2[0][i] = s0; g_s2[1][i] = s1; g_s2[2][i] = s2;
    }
}

// ---------------------------------------------------------------------------
// Finalize: out[0,:] = E_grid; out[1+x,:] = max(F,0)
// Lower rows (<1024) end in buffer 0 after 2 sweeps (0->1->0);
// upper rows (>=1024) end in buffer 0 after 4 sweeps. Row 2047 set in both.
// ---------------------------------------------------------------------------
__global__ __launch_bounds__(256) void final_kernel(
    const float* __restrict__ E, float* __restrict__ out)
{
    int i = blockIdx.x * blockDim.x + threadIdx.x;
    if (i >= NE) return;
    out[i] = E[i];
#pragma unroll
    for (int x = 0; x < NX; x++) {
        float f = g_F[0][x][i];
        out[(x + 1) * NE + i] = (f > 0.0f) ? f : 0.0f;
    }
}

extern "C" void kernel_launch(void* const* d_in, const int* in_sizes, int n_in,
                              void* d_out, int out_size)
{
    const float* E  = (const float*)d_in[0];
    const float* R  = (const float*)d_in[1];
    const float* K  = (const float*)d_in[2];
    const float* S0 = (const float*)d_in[3];
    const float* SC = (const float*)d_in[4];
    float* out = (float*)d_out;

    // Setup (8 blocks) + full upper-triangle L2 prefetch (1024 blocks).
    setup_prefetch_kernel<<<8 + 1024, 256>>>(E, R, K, S0, SC);

    // Phase 1: Jacobi on upper half (rows 1024..2046), j in (i, 2048).
    // 4 sweeps: 0->1, 1->0, 0->1, 1->0  (final in buffer 0)
    sweep_kernel<<<512, 256>>>(K, 0, 1, NE/2, NE-2, NE, 0);
    sweep_kernel<<<512, 256>>>(K, 1, 0, NE/2, NE-2, NE, 0);
    sweep_kernel<<<512, 256>>>(K, 0, 1, NE/2, NE-2, NE, 0);
    sweep_kernel<<<512, 256>>>(K, 1, 0, NE/2, NE-2, NE, 0);

    // Fold upper-half contributions into lower rows' RHS (reads buffer 0).
    accum_kernel<<<NE/2, 256>>>(K, 0);

    // Phase 2: Jacobi on lower half (rows 0..1023), j in (i, 1024), RHS = s2.
    // 2 sweeps: 0->1, 1->0  (final in buffer 0; ρ_low ≈ 0.01 → residual ~1e-6)
    sweep_kernel<<<512, 256>>>(K, 0, 1, 0, NE/2 - 1, NE/2, 1);
    sweep_kernel<<<512, 256>>>(K, 1, 0, 0, NE/2 - 1, NE/2, 1);

    final_kernel<<<(NE + 255) / 256, 256>>>(E, out);
}

// round 8
// speedup vs baseline: 1.9523x; 1.3169x over previous
#include <cuda_runtime.h>
#include <math.h>

#define NE 2048
#define NX 3

// Scratch (allocation-free): all __device__ globals.
__device__ float g_s[NX][NE];        // static RHS (SC + last-column terms)
__device__ float g_s2[NX][NE];       // extended RHS for lower rows
__device__ float g_Binv[NX*NX][NE];  // per-bin 3x3 inverse of B_i
__device__ float g_c[NE];            // c_j = dy*E_j
__device__ float g_F[2][NX][NE];     // double-buffered solution
__device__ float g_wF[2][NX][NE];    // double-buffered c_j*F_j (col NE-1 == 0)

__device__ __forceinline__ float4 ld4(const float* __restrict__ p, int j) {
    return *reinterpret_cast<const float4*>(p + j);
}

#define DECLARE_K_STREAMS(K, i)                                                \
    const float* __restrict__ k00 = K + ((size_t)((0*NX+0)*NE + i))*NE;        \
    const float* __restrict__ k01 = K + ((size_t)((0*NX+1)*NE + i))*NE;        \
    const float* __restrict__ k02 = K + ((size_t)((0*NX+2)*NE + i))*NE;        \
    const float* __restrict__ k10 = K + ((size_t)((1*NX+0)*NE + i))*NE;        \
    const float* __restrict__ k11 = K + ((size_t)((1*NX+1)*NE + i))*NE;        \
    const float* __restrict__ k12 = K + ((size_t)((1*NX+2)*NE + i))*NE;        \
    const float* __restrict__ k20 = K + ((size_t)((2*NX+0)*NE + i))*NE;        \
    const float* __restrict__ k21 = K + ((size_t)((2*NX+1)*NE + i))*NE;        \
    const float* __restrict__ k22 = K + ((size_t)((2*NX+2)*NE + i))*NE;

#define ACCUM(JB, W0, W1, W2)                                                  \
    do {                                                                       \
        float4 kk;                                                             \
        kk = ld4(k00, JB); y0 += kk.x*W0.x + kk.y*W0.y + kk.z*W0.z + kk.w*W0.w;\
        kk = ld4(k01, JB); y0 += kk.x*W1.x + kk.y*W1.y + kk.z*W1.z + kk.w*W1.w;\
        kk = ld4(k02, JB); y0 += kk.x*W2.x + kk.y*W2.y + kk.z*W2.z + kk.w*W2.w;\
        kk = ld4(k10, JB); y1 += kk.x*W0.x + kk.y*W0.y + kk.z*W0.z + kk.w*W0.w;\
        kk = ld4(k11, JB); y1 += kk.x*W1.x + kk.y*W1.y + kk.z*W1.z + kk.w*W1.w;\
        kk = ld4(k12, JB); y1 += kk.x*W2.x + kk.y*W2.y + kk.z*W2.z + kk.w*W2.w;\
        kk = ld4(k20, JB); y2 += kk.x*W0.x + kk.y*W0.y + kk.z*W0.z + kk.w*W0.w;\
        kk = ld4(k21, JB); y2 += kk.x*W1.x + kk.y*W1.y + kk.z*W1.z + kk.w*W1.w;\
        kk = ld4(k22, JB); y2 += kk.x*W2.x + kk.y*W2.y + kk.z*W2.z + kk.w*W2.w;\
    } while (0)

// ---------------------------------------------------------------------------
// Setup: dy, src_last, F[:,NE-1], c_j, B_i^{-1}, s, initial guess F0 = Binv*s
// ---------------------------------------------------------------------------
__global__ __launch_bounds__(128) void setup_kernel(
    const float* __restrict__ E, const float* __restrict__ R,
    const float* __restrict__ K, const float* __restrict__ S0,
    const float* __restrict__ SC)
{
    int i = blockIdx.x * 128 + threadIdx.x;
    if (i >= NE) return;

    const float dy = logf(E[NE-1] / E[0]) / (float)(NE - 1);

    float srcl[NX];
#pragma unroll
    for (int p = 0; p < NX; p++) srcl[p] = S0[p] / R[p*NE + NE-1];

    float Flast[NX];
#pragma unroll
    for (int x = 0; x < NX; x++) {
        float acc = SC[x*NE + NE-1];
#pragma unroll
        for (int p = 0; p < NX; p++)
            acc += K[((size_t)((x*NX + p)*NE + (NE-1)))*NE + (NE-1)] * srcl[p];
        Flast[x] = acc / R[x*NE + NE-1];
    }

    if (i == NE-1) {
#pragma unroll
        for (int x = 0; x < NX; x++) {
            g_F[0][x][NE-1] = Flast[x];
            g_F[1][x][NE-1] = Flast[x];
            g_wF[0][x][NE-1] = 0.0f;
            g_wF[1][x][NE-1] = 0.0f;
        }
        return;
    }

    const float ci = dy * E[i];
    g_c[i] = ci;
    const float w_last = 0.5f * dy * E[NE-1];

    float Bm[3][3];
    float sv[NX];
#pragma unroll
    for (int x = 0; x < NX; x++) {
        float acc = SC[x*NE + i];
#pragma unroll
        for (int p = 0; p < NX; p++) {
            size_t rb = ((size_t)((x*NX + p)*NE + i)) * NE;
            float Kii = K[rb + i];
            float Kil = K[rb + NE-1];
            Bm[x][p] = -0.5f * ci * Kii + ((x == p) ? R[x*NE + i] : 0.0f);
            acc += Kil * (w_last * Flast[p] + srcl[p]);
        }
        sv[x] = acc;
    }

    float c00 = Bm[1][1]*Bm[2][2] - Bm[1][2]*Bm[2][1];
    float c01 = Bm[1][2]*Bm[2][0] - Bm[1][0]*Bm[2][2];
    float c02 = Bm[1][0]*Bm[2][1] - Bm[1][1]*Bm[2][0];
    float det = Bm[0][0]*c00 + Bm[0][1]*c01 + Bm[0][2]*c02;
    float id  = 1.0f / det;
    float inv[3][3];
    inv[0][0] = c00 * id;
    inv[0][1] = (Bm[0][2]*Bm[2][1] - Bm[0][1]*Bm[2][2]) * id;
    inv[0][2] = (Bm[0][1]*Bm[1][2] - Bm[0][2]*Bm[1][1]) * id;
    inv[1][0] = c01 * id;
    inv[1][1] = (Bm[0][0]*Bm[2][2] - Bm[0][2]*Bm[2][0]) * id;
    inv[1][2] = (Bm[0][2]*Bm[1][0] - Bm[0][0]*Bm[1][2]) * id;
    inv[2][0] = c02 * id;
    inv[2][1] = (Bm[0][1]*Bm[2][0] - Bm[0][0]*Bm[2][1]) * id;
    inv[2][2] = (Bm[0][0]*Bm[1][1] - Bm[0][1]*Bm[1][0]) * id;

#pragma unroll
    for (int x = 0; x < NX; x++) {
        g_s[x][i] = sv[x];
#pragma unroll
        for (int p = 0; p < NX; p++) g_Binv[x*NX + p][i] = inv[x][p];
    }

#pragma unroll
    for (int x = 0; x < NX; x++) {
        float f = inv[x][0]*sv[0] + inv[x][1]*sv[1] + inv[x][2]*sv[2];
        g_F[0][x][i]  = f;
        g_wF[0][x][i] = ci * f;
    }
}

// ---------------------------------------------------------------------------
// One sweep, ONE ROW PER BLOCK (128 threads): all rows of a phase run in a
// single resident wave, so the sweep is L2-BW bound, not pipeline bound.
//   y = sum_{p, j in (i, col_hi)} K[x][p][i][j] * wF[p][j]
//   F_new[:,i] = Binv_i * (s_in[:,i] + y)
// ---------------------------------------------------------------------------
__global__ __launch_bounds__(128) void sweep_kernel(
    const float* __restrict__ K, int src, int dst,
    int row_lo, int col_hi, int use_s2)
{
    __shared__ float red[3][4];
    int tid  = threadIdx.x;
    int lane = tid & 31;
    int warp = tid >> 5;
    int i    = row_lo + blockIdx.x;

    const float* __restrict__ wf0 = g_wF[src][0];
    const float* __restrict__ wf1 = g_wF[src][1];
    const float* __restrict__ wf2 = g_wF[src][2];
    DECLARE_K_STREAMS(K, i)

    float y0 = 0.f, y1 = 0.f, y2 = 0.f;
    int jv = (i + 1) & ~3;           // 16B-aligned start
    int jb = jv + 4 * tid;

    if (jb < col_hi) {
        // first pass: mask elements with j <= i (only low-tid chunk can hit)
        float4 w0 = ld4(wf0, jb), w1 = ld4(wf1, jb), w2 = ld4(wf2, jb);
        if (jb + 0 <= i) { w0.x = 0.f; w1.x = 0.f; w2.x = 0.f; }
        if (jb + 1 <= i) { w0.y = 0.f; w1.y = 0.f; w2.y = 0.f; }
        if (jb + 2 <= i) { w0.z = 0.f; w1.z = 0.f; w2.z = 0.f; }
        if (jb + 3 <= i) { w0.w = 0.f; w1.w = 0.f; w2.w = 0.f; }
        ACCUM(jb, w0, w1, w2);
        jb += 4 * 128;
    }
#pragma unroll 2
    for (; jb < col_hi; jb += 4 * 128) {
        float4 w0 = ld4(wf0, jb), w1 = ld4(wf1, jb), w2 = ld4(wf2, jb);
        ACCUM(jb, w0, w1, w2);
    }

    // warp reduce + 4-warp smem reduce
#pragma unroll
    for (int o = 16; o > 0; o >>= 1) {
        y0 += __shfl_xor_sync(0xffffffffu, y0, o);
        y1 += __shfl_xor_sync(0xffffffffu, y1, o);
        y2 += __shfl_xor_sync(0xffffffffu, y2, o);
    }
    if (lane == 0) { red[0][warp] = y0; red[1][warp] = y1; red[2][warp] = y2; }
    __syncthreads();

    if (tid == 0) {
        float s0, s1, s2;
        if (use_s2) { s0 = g_s2[0][i]; s1 = g_s2[1][i]; s2 = g_s2[2][i]; }
        else        { s0 = g_s [0][i]; s1 = g_s [1][i]; s2 = g_s [2][i]; }
#pragma unroll
        for (int w = 0; w < 4; w++) {
            s0 += red[0][w]; s1 += red[1][w]; s2 += red[2][w];
        }
        float f0 = g_Binv[0][i]*s0 + g_Binv[1][i]*s1 + g_Binv[2][i]*s2;
        float f1 = g_Binv[3][i]*s0 + g_Binv[4][i]*s1 + g_Binv[5][i]*s2;
        float f2 = g_Binv[6][i]*s0 + g_Binv[7][i]*s1 + g_Binv[8][i]*s2;
        float ci = g_c[i];
        g_F[dst][0][i]  = f0;  g_wF[dst][0][i] = ci * f0;
        g_F[dst][1][i]  = f1;  g_wF[dst][1][i] = ci * f1;
        g_F[dst][2][i]  = f2;  g_wF[dst][2][i] = ci * f2;
    }
}

// ---------------------------------------------------------------------------
// Accumulate solved upper half into lower rows' RHS:
// g_s2[:,i] = g_s[:,i] + sum_{p, j in [1024,2048)} K[x][p][i][j]*wF[p][j]
// One block per row, 256 threads x 4 = exactly 1024 columns, single pass.
// ---------------------------------------------------------------------------
__global__ __launch_bounds__(256) void accum_kernel(
    const float* __restrict__ K, int src)
{
    __shared__ float red[3][8];
    int tid = threadIdx.x, lane = tid & 31, warp = tid >> 5;
    int i = blockIdx.x;              // 0..1023

    const float* __restrict__ wf0 = g_wF[src][0];
    const float* __restrict__ wf1 = g_wF[src][1];
    const float* __restrict__ wf2 = g_wF[src][2];
    DECLARE_K_STREAMS(K, i)

    float y0 = 0.f, y1 = 0.f, y2 = 0.f;
    int jb = NE/2 + 4 * tid;
    {
        float4 w0 = ld4(wf0, jb), w1 = ld4(wf1, jb), w2 = ld4(wf2, jb);
        ACCUM(jb, w0, w1, w2);
    }

#pragma unroll
    for (int o = 16; o > 0; o >>= 1) {
        y0 += __shfl_xor_sync(0xffffffffu, y0, o);
        y1 += __shfl_xor_sync(0xffffffffu, y1, o);
        y2 += __shfl_xor_sync(0xffffffffu, y2, o);
    }
    if (lane == 0) { red[0][warp] = y0; red[1][warp] = y1; red[2][warp] = y2; }
    __syncthreads();

    if (tid == 0) {
        float s0 = g_s[0][i], s1 = g_s[1][i], s2 = g_s[2][i];
#pragma unroll
        for (int w = 0; w < 8; w++) {
            s0 += red[0][w]; s1 += red[1][w]; s2 += red[2][w];
        }
        g_s2[0][i] = s0; g_s2[1][i] = s1; g_s2[2][i] = s2;
    }
}

// ---------------------------------------------------------------------------
// Finalize: out[0,:] = E_grid; out[1+x,:] = max(F,0). Both halves end in buf 0.
// ---------------------------------------------------------------------------
__global__ __launch_bounds__(256) void final_kernel(
    const float* __restrict__ E, float* __restrict__ out)
{
    int i = blockIdx.x * blockDim.x + threadIdx.x;
    if (i >= NE) return;
    out[i] = E[i];
#pragma unroll
    for (int x = 0; x < NX; x++) {
        float f = g_F[0][x][i];
        out[(x + 1) * NE + i] = (f > 0.0f) ? f : 0.0f;
    }
}

extern "C" void kernel_launch(void* const* d_in, const int* in_sizes, int n_in,
                              void* d_out, int out_size)
{
    const float* E  = (const float*)d_in[0];
    const float* R  = (const float*)d_in[1];
    const float* K  = (const float*)d_in[2];
    const float* S0 = (const float*)d_in[3];
    const float* SC = (const float*)d_in[4];
    float* out = (float*)d_out;

    setup_kernel<<<NE/128, 128>>>(E, R, K, S0, SC);

    // Phase 1: Jacobi on upper half (rows 1024..2046), j in (i, 2048).
    // One block per row; 4 sweeps: 0->1, 1->0, 0->1, 1->0 (final in buffer 0).
    sweep_kernel<<<NE/2 - 1, 128>>>(K, 0, 1, NE/2, NE, 0);
    sweep_kernel<<<NE/2 - 1, 128>>>(K, 1, 0, NE/2, NE, 0);
    sweep_kernel<<<NE/2 - 1, 128>>>(K, 0, 1, NE/2, NE, 0);
    sweep_kernel<<<NE/2 - 1, 128>>>(K, 1, 0, NE/2, NE, 0);

    // Fold upper-half contributions into lower rows' RHS (reads buffer 0).
    accum_kernel<<<NE/2, 256>>>(K, 0);

    // Phase 2: Jacobi on lower half (rows 0..1023), j in (i, 1024), RHS = s2.
    // 2 sweeps: 0->1, 1->0 (final in buffer 0).
    sweep_kernel<<<NE/2, 128>>>(K, 0, 1, 0, NE/2, 1);
    sweep_kernel<<<NE/2, 128>>>(K, 1, 0, 0, NE/2, 1);

    final_kernel<<<(NE + 255) / 256, 256>>>(E, out);
}